// round 11
// baseline (speedup 1.0000x reference)
#include <cuda_runtime.h>
#include <cuda_bf16.h>
#include <math.h>
#include <stdint.h>

// Problem dims (fixed)
#define BDIM 128
#define TDIM 512
#define IDIM 512
#define HDIM 1024
#define G4   4096
#define ODIM 512
#define MROWS (BDIM * TDIM)  // 65536

typedef unsigned long long ull;

// Packed dual-fp32 FMA (B300 FFMA2) — exact fp32, 2x throughput, only via PTX.
__device__ __forceinline__ void ffma2(ull& d, ull a, ull b) {
    asm("fma.rn.f32x2 %0, %1, %2, %0;" : "+l"(d) : "l"(a), "l"(b));
}
__device__ __forceinline__ float lo32(ull u) { return __uint_as_float((unsigned)u); }
__device__ __forceinline__ float hi32(ull u) { return __uint_as_float((unsigned)(u >> 32)); }

// ---------------- Scratch (static device allocations; no cudaMalloc) ----------
__device__ float g_xg[(size_t)TDIM * BDIM * G4];     // [T,B,4H] 1 GiB
__device__ float g_hout[(size_t)BDIM * TDIM * HDIM]; // [B,T,H] 256 MiB
__device__ float g_hA[BDIM * HDIM];                  // recurrent h double buffer
__device__ float g_hB[BDIM * HDIM];
// bf16 split-precision operands for tensor-core GEMMs
__device__ __nv_bfloat16 g_Ahi[(size_t)MROWS * HDIM];  // 128 MiB
__device__ __nv_bfloat16 g_Alo[(size_t)MROWS * HDIM];  // 128 MiB
__device__ __nv_bfloat16 g_Whi[(size_t)G4 * HDIM];     // 8 MiB
__device__ __nv_bfloat16 g_Wlo[(size_t)G4 * HDIM];     // 8 MiB

// ---------------- Grid barrier --------------------------------------------
__device__ unsigned g_cnt = 0;
__device__ volatile unsigned g_gen = 0;

__device__ __forceinline__ void grid_barrier(unsigned nb) {
    __syncthreads();
    if (threadIdx.x == 0) {
        unsigned gen = g_gen;
        __threadfence();
        if (atomicAdd(&g_cnt, 1u) == nb - 1u) {
            g_cnt = 0;
            __threadfence();
            g_gen = gen + 1u;
        } else {
            while (g_gen == gen) { }
        }
    }
    __syncthreads();
}

__device__ __forceinline__ float sigmoidf_(float x) {
    return 1.0f / (1.0f + __expf(-x));
}

// ===================== baseline-PTX tensor-core helpers ====================
__device__ __forceinline__ uint32_t smem_u32(const void* p) {
    uint32_t a;
    asm("{ .reg .u64 t; cvta.to.shared.u64 t, %1; cvt.u32.u64 %0, t; }" : "=r"(a) : "l"(p));
    return a;
}
#define SWZ(o) ((o) ^ ((((unsigned)(o)) >> 3) & 0x70u))

__device__ __forceinline__ void ldsm_x4(uint32_t r[4], uint32_t addr) {
    asm volatile("ldmatrix.sync.aligned.m8n8.x4.shared.b16 {%0,%1,%2,%3}, [%4];"
                 : "=r"(r[0]), "=r"(r[1]), "=r"(r[2]), "=r"(r[3]) : "r"(addr));
}
__device__ __forceinline__ void mma_bf16(float c[4], const uint32_t a[4], const uint32_t b[2]) {
    asm volatile(
        "mma.sync.aligned.m16n8k16.row.col.f32.bf16.bf16.f32 "
        "{%0,%1,%2,%3}, {%4,%5,%6,%7}, {%8,%9}, {%0,%1,%2,%3};"
        : "+f"(c[0]), "+f"(c[1]), "+f"(c[2]), "+f"(c[3])
        : "r"(a[0]), "r"(a[1]), "r"(a[2]), "r"(a[3]), "r"(b[0]), "r"(b[1]));
}
__device__ __forceinline__ void cp16(uint32_t saddr, const void* g) {
    asm volatile("cp.async.cg.shared.global [%0], [%1], 16;" :: "r"(saddr), "l"(g));
}
#define CP_COMMIT() asm volatile("cp.async.commit_group;" ::: "memory")
#define CP_WAIT(n)  asm volatile("cp.async.wait_group %0;" :: "n"(n) : "memory")

// ---------------- bf16 split kernel ----------------------------------------
__global__ void split_bf16(const float* __restrict__ in,
                           __nv_bfloat16* __restrict__ hi,
                           __nv_bfloat16* __restrict__ lo, size_t n2) {
    size_t i = (size_t)blockIdx.x * blockDim.x + threadIdx.x;
    size_t stride = (size_t)gridDim.x * blockDim.x;
    const float2* in2 = (const float2*)in;
    __nv_bfloat162* h2 = (__nv_bfloat162*)hi;
    __nv_bfloat162* l2 = (__nv_bfloat162*)lo;
    for (; i < n2; i += stride) {
        float2 v = in2[i];
        __nv_bfloat16 hx = __float2bfloat16_rn(v.x);
        __nv_bfloat16 hy = __float2bfloat16_rn(v.y);
        float lx = v.x - __bfloat162float(hx);
        float ly = v.y - __bfloat162float(hy);
        __nv_bfloat162 hh; hh.x = hx; hh.y = hy;
        __nv_bfloat162 ll; ll.x = __float2bfloat16_rn(lx); ll.y = __float2bfloat16_rn(ly);
        h2[i] = hh;
        l2[i] = ll;
    }
}

// ---------------- HMMA split-precision GEMM --------------------------------
// C[M,N] = A[M,K] @ W[N,K]^T + b1 + b2 (fp32 via bf16 hi/lo 3-term split).
// CTA: 256 threads (8 warps), tile 128(M) x 128(N); warp tile 32x64.
#define GM_TILE_B   16384                 // 128 rows x 128 bytes
#define GM_STAGE_B  (4 * GM_TILE_B)       // 64 KiB
#define GM_SMEM     (1024 + 2 * GM_STAGE_B)

__global__ __launch_bounds__(256, 1) void gemm_mma(
    const __nv_bfloat16* __restrict__ Ahi, const __nv_bfloat16* __restrict__ Alo,
    const __nv_bfloat16* __restrict__ Bhi, const __nv_bfloat16* __restrict__ Blo,
    const float* __restrict__ b1, const float* __restrict__ b2,
    float* __restrict__ C, int K, int N, int swap)
{
    extern __shared__ char dsm[];
    const int tid = threadIdx.x;
    const int lane = tid & 31;
    const int warp = tid >> 5;
    const int m0 = blockIdx.y << 7;
    const int n0 = blockIdx.x << 7;
    const int wm = (warp >> 1) << 5;   // 0,32,64,96
    const int wn = (warp & 1) << 6;    // 0,64

    uint32_t sb = (smem_u32(dsm) + 1023u) & ~1023u;

    const int lrow = tid & 127;
    const int lcp  = (tid >> 7) << 2;  // chunk base 0 or 4 (x16B)

    auto load_tile = [&](uint32_t sdst, const __nv_bfloat16* gsrc, int row0, int kc) {
        const __nv_bfloat16* g = gsrc + (size_t)(row0 + lrow) * K + kc * 64 + lcp * 8;
        uint32_t ob = (uint32_t)lrow * 128u + (uint32_t)lcp * 16u;
#pragma unroll
        for (int j = 0; j < 4; j++)
            cp16(sdst + SWZ(ob + j * 16u), g + j * 8);
    };
    auto load_stage = [&](uint32_t stage, int kc) {
        uint32_t base = sb + stage * GM_STAGE_B;
        load_tile(base,                Ahi, m0, kc);
        load_tile(base + GM_TILE_B,    Alo, m0, kc);
        load_tile(base + 2 * GM_TILE_B, Bhi, n0, kc);
        load_tile(base + 3 * GM_TILE_B, Blo, n0, kc);
        CP_COMMIT();
    };

    float acc[2][8][4];
#pragma unroll
    for (int mf = 0; mf < 2; mf++)
#pragma unroll
        for (int f = 0; f < 8; f++)
#pragma unroll
            for (int e = 0; e < 4; e++) acc[mf][f][e] = 0.0f;

    const uint32_t a_off = (uint32_t)(wm + (lane & 15)) * 128u + (uint32_t)(lane >> 4) * 16u;
    const uint32_t b_row = (uint32_t)(wn + ((lane >> 4) << 3) + (lane & 7));
    const uint32_t b_off = b_row * 128u + (uint32_t)((lane >> 3) & 1) * 16u;

    const int nc = K >> 6;
    load_stage(0, 0);

#pragma unroll 1
    for (int c = 0; c < nc; ++c) {
        if (c + 1 < nc) load_stage((c + 1) & 1, c + 1);
        if (c + 1 < nc) { CP_WAIT(1); } else { CP_WAIT(0); }
        __syncthreads();

        uint32_t base = sb + (uint32_t)(c & 1) * GM_STAGE_B;
        uint32_t pAh = base;
        uint32_t pAl = base + GM_TILE_B;
        uint32_t pBh = base + 2 * GM_TILE_B;
        uint32_t pBl = base + 3 * GM_TILE_B;

#pragma unroll
        for (int ks = 0; ks < 4; ks++) {
            uint32_t ko = (uint32_t)ks * 32u;
            uint32_t ahi[2][4], alo[2][4];
#pragma unroll
            for (int mf = 0; mf < 2; mf++) {
                uint32_t off = a_off + (uint32_t)(mf << 11) + ko;
                ldsm_x4(ahi[mf], pAh + SWZ(off));
                ldsm_x4(alo[mf], pAl + SWZ(off));
            }
            uint32_t bhi[8][2], blo[8][2];
#pragma unroll
            for (int nq = 0; nq < 4; nq++) {
                uint32_t off = b_off + (uint32_t)(nq << 11) + ko;
                uint32_t r[4];
                ldsm_x4(r, pBh + SWZ(off));
                bhi[2 * nq][0] = r[0]; bhi[2 * nq][1] = r[1];
                bhi[2 * nq + 1][0] = r[2]; bhi[2 * nq + 1][1] = r[3];
                ldsm_x4(r, pBl + SWZ(off));
                blo[2 * nq][0] = r[0]; blo[2 * nq][1] = r[1];
                blo[2 * nq + 1][0] = r[2]; blo[2 * nq + 1][1] = r[3];
            }
#pragma unroll
            for (int mf = 0; mf < 2; mf++)
#pragma unroll
                for (int f = 0; f < 8; f++) {
                    mma_bf16(acc[mf][f], ahi[mf], bhi[f]);
                    mma_bf16(acc[mf][f], ahi[mf], blo[f]);
                    mma_bf16(acc[mf][f], alo[mf], bhi[f]);
                }
        }
        __syncthreads();
    }

#pragma unroll
    for (int mf = 0; mf < 2; mf++) {
        int mA = m0 + wm + mf * 16 + (lane >> 2);
        int mB = mA + 8;
        int rA = swap ? ((mA & (TDIM - 1)) * BDIM + (mA >> 9)) : mA;
        int rB = swap ? ((mB & (TDIM - 1)) * BDIM + (mB >> 9)) : mB;
        float* CA = C + (size_t)rA * N;
        float* CB = C + (size_t)rB * N;
#pragma unroll
        for (int f = 0; f < 8; f++) {
            int n = n0 + wn + f * 8 + ((lane & 3) << 1);
            float bb0 = b1[n] + (b2 ? b2[n] : 0.0f);
            float bb1 = b1[n + 1] + (b2 ? b2[n + 1] : 0.0f);
            float2 v0 = make_float2(acc[mf][f][0] + bb0, acc[mf][f][1] + bb1);
            float2 v1 = make_float2(acc[mf][f][2] + bb0, acc[mf][f][3] + bb1);
            *(float2*)(CA + n) = v0;
            *(float2*)(CB + n) = v1;
        }
    }
}

// ---------------- Persistent LSTM scan (FFMA2, 256 threads) ----------------
// 128 CTAs (4 b-tiles x 32 h-tiles) x 256 threads (8 warps = 2/SMSP for
// latency hiding). Warp w -> b rows 4w..4w+3; lane -> 4 cols. Per k:
// 2 broadcast A-LDS (dup pairs) + 1 B-LDS + 8 FFMA2.
__global__ __launch_bounds__(256, 1) void lstm_scan(const float* __restrict__ Whh)
{
    __shared__ alignas(16) float AsD[2][16][68];   // dup A: [k][2*row(+0/1)], pad
    __shared__ alignas(16) float Bs[2][16][132];   // [k][col], pad (16B-aligned rows)
    __shared__ alignas(16) float gsm[32][128];     // gates staging
    __shared__ float csm[32][32];                  // cell state (persistent)

    const int tid = threadIdx.x;
    const int b0 = (blockIdx.x >> 5) << 5;  // 0,32,64,96
    const int h0 = (blockIdx.x & 31) << 5;  // 0..992
    const unsigned nb = gridDim.x;

    // zero c and the initial h buffer (this CTA's (b,h) block)
    for (int q = tid; q < 1024; q += 256) {
        csm[q >> 5][q & 31] = 0.0f;
        g_hA[(b0 + (q >> 5)) * HDIM + h0 + (q & 31)] = 0.0f;
    }
    __threadfence();
    grid_barrier(nb);

    // compute mapping: warp -> 4 b-rows, lane -> 4 cols
    const int w = tid >> 5;          // 0..7
    const int l = tid & 31;          // 0..31

    // A loader (threads 0..127): 32 rows x 16 k per tile
    const int ab = tid >> 2;         // 0..31 (valid when tid<128)
    const int ak = (tid & 3) << 2;   // 0,4,8,12

    // B loader (all 256 threads): 2 cols each (c2 and c2+64), 4 k-quad
    const int c2 = tid >> 2;         // 0..63
    const int kb = (tid & 3) << 2;   // 0,4,8,12
    const int colA = c2;
    const int colB = c2 + 64;
    const int wrowA = ((colA >> 5) << 10) + h0 + (colA & 31);
    const int wrowB = ((colB >> 5) << 10) + h0 + (colB & 31);
    const float* WpA = Whh + (size_t)wrowA * HDIM + kb;
    const float* WpB = Whh + (size_t)wrowB * HDIM + kb;

    // elementwise mapping: 4 cells per thread
    const int eb = tid >> 3;           // 0..31
    const int eh = (tid & 7) << 2;     // 0..28

#pragma unroll 1
    for (int t = 0; t < TDIM; ++t) {
        const float* hp = (t & 1) ? g_hB : g_hA;
        float* hn = (t & 1) ? g_hA : g_hB;
        const float* Ap = hp + (b0 + ab) * HDIM + ak;

        // Prefetch this step's xg slices early (hide DRAM latency behind GEMM).
        const size_t xb = ((size_t)t * BDIM + b0 + eb) * G4 + h0 + eh;
        float4 xi = __ldcs((const float4*)&g_xg[xb]);
        float4 xf = __ldcs((const float4*)&g_xg[xb + 1024]);
        float4 xgv = __ldcs((const float4*)&g_xg[xb + 2048]);
        float4 xo = __ldcs((const float4*)&g_xg[xb + 3072]);

        // prologue: k-tile 0
        float4 ra = make_float4(0.f, 0.f, 0.f, 0.f);
        if (tid < 128) ra = __ldcg((const float4*)Ap);
        float4 rbA = *(const float4*)WpA;
        float4 rbB = *(const float4*)WpB;
        if (tid < 128) {
            AsD[0][ak + 0][2 * ab] = ra.x; AsD[0][ak + 0][2 * ab + 1] = ra.x;
            AsD[0][ak + 1][2 * ab] = ra.y; AsD[0][ak + 1][2 * ab + 1] = ra.y;
            AsD[0][ak + 2][2 * ab] = ra.z; AsD[0][ak + 2][2 * ab + 1] = ra.z;
            AsD[0][ak + 3][2 * ab] = ra.w; AsD[0][ak + 3][2 * ab + 1] = ra.w;
        }
        Bs[0][kb + 0][colA] = rbA.x; Bs[0][kb + 1][colA] = rbA.y;
        Bs[0][kb + 2][colA] = rbA.z; Bs[0][kb + 3][colA] = rbA.w;
        Bs[0][kb + 0][colB] = rbB.x; Bs[0][kb + 1][colB] = rbB.y;
        Bs[0][kb + 2][colB] = rbB.z; Bs[0][kb + 3][colB] = rbB.w;
        __syncthreads();

        ull acc[4][2];
#pragma unroll
        for (int i = 0; i < 4; i++) { acc[i][0] = 0ULL; acc[i][1] = 0ULL; }

        int cur = 0;
#pragma unroll 1
        for (int kt = 0; kt < 64; ++kt) {
            if (kt < 63) {
                int ko = (kt + 1) << 4;
                if (tid < 128) ra = __ldcg((const float4*)(Ap + ko));
                rbA = *(const float4*)(WpA + ko);
                rbB = *(const float4*)(WpB + ko);
            }
#pragma unroll
            for (int k = 0; k < 16; ++k) {
                ulonglong2 a01 = *(const ulonglong2*)&AsD[cur][k][8 * w];
                ulonglong2 a23 = *(const ulonglong2*)&AsD[cur][k][8 * w + 4];
                ulonglong2 bb = *(const ulonglong2*)&Bs[cur][k][4 * l];
                ffma2(acc[0][0], a01.x, bb.x); ffma2(acc[0][1], a01.x, bb.y);
                ffma2(acc[1][0], a01.y, bb.x); ffma2(acc[1][1], a01.y, bb.y);
                ffma2(acc[2][0], a23.x, bb.x); ffma2(acc[2][1], a23.x, bb.y);
                ffma2(acc[3][0], a23.y, bb.x); ffma2(acc[3][1], a23.y, bb.y);
            }
            if (kt < 63) {
                cur ^= 1;
                if (tid < 128) {
                    AsD[cur][ak + 0][2 * ab] = ra.x; AsD[cur][ak + 0][2 * ab + 1] = ra.x;
                    AsD[cur][ak + 1][2 * ab] = ra.y; AsD[cur][ak + 1][2 * ab + 1] = ra.y;
                    AsD[cur][ak + 2][2 * ab] = ra.z; AsD[cur][ak + 2][2 * ab + 1] = ra.z;
                    AsD[cur][ak + 3][2 * ab] = ra.w; AsD[cur][ak + 3][2 * ab + 1] = ra.w;
                }
                Bs[cur][kb + 0][colA] = rbA.x; Bs[cur][kb + 1][colA] = rbA.y;
                Bs[cur][kb + 2][colA] = rbA.z; Bs[cur][kb + 3][colA] = rbA.w;
                Bs[cur][kb + 0][colB] = rbB.x; Bs[cur][kb + 1][colB] = rbB.y;
                Bs[cur][kb + 2][colB] = rbB.z; Bs[cur][kb + 3][colB] = rbB.w;
                __syncthreads();
            }
        }

        // stage gates to smem for the gate-regrouped elementwise
#pragma unroll
        for (int i = 0; i < 4; i++) {
            *(float4*)&gsm[4 * w + i][4 * l] =
                make_float4(lo32(acc[i][0]), hi32(acc[i][0]),
                            lo32(acc[i][1]), hi32(acc[i][1]));
        }
        __syncthreads();

        {
            const float* pxi = (const float*)&xi;
            const float* pxf = (const float*)&xf;
            const float* pxg = (const float*)&xgv;
            const float* pxo = (const float*)&xo;

            float h4[4];
#pragma unroll
            for (int q = 0; q < 4; q++) {
                int hh = eh + q;
                float gi = gsm[eb][hh]      + pxi[q];
                float gf = gsm[eb][32 + hh] + pxf[q];
                float gg = gsm[eb][64 + hh] + pxg[q];
                float go = gsm[eb][96 + hh] + pxo[q];
                gi = sigmoidf_(gi);
                gf = sigmoidf_(gf);
                gg = tanhf(gg);
                go = sigmoidf_(go);
                float c = fmaf(gf, csm[eb][hh], gi * gg);
                csm[eb][hh] = c;
                h4[q] = go * tanhf(c);
            }
            float4 hv = make_float4(h4[0], h4[1], h4[2], h4[3]);
            *(float4*)&hn[(b0 + eb) * HDIM + h0 + eh] = hv;
            *(float4*)&g_hout[((size_t)(b0 + eb) * TDIM + t) * HDIM + h0 + eh] = hv;
        }
        __threadfence();
        grid_barrier(nb);
    }
}

// ---------------- Launch orchestration -------------------------------------
extern "C" void kernel_launch(void* const* d_in, const int* in_sizes, int n_in,
                              void* d_out, int out_size)
{
    (void)in_sizes; (void)n_in; (void)out_size;
    const float* x    = (const float*)d_in[0];
    const float* Wih0 = (const float*)d_in[1];
    const float* Whh0 = (const float*)d_in[2];
    const float* bih0 = (const float*)d_in[3];
    const float* bhh0 = (const float*)d_in[4];
    const float* Wih1 = (const float*)d_in[5];
    const float* Whh1 = (const float*)d_in[6];
    const float* bih1 = (const float*)d_in[7];
    const float* bhh1 = (const float*)d_in[8];
    const float* Wlin = (const float*)d_in[9];
    const float* blin = (const float*)d_in[10];
    float* out = (float*)d_out;

    void *pxg = nullptr, *phout = nullptr;
    void *pAhi = nullptr, *pAlo = nullptr, *pWhi = nullptr, *pWlo = nullptr;
    cudaGetSymbolAddress(&pxg, g_xg);
    cudaGetSymbolAddress(&phout, g_hout);
    cudaGetSymbolAddress(&pAhi, g_Ahi);
    cudaGetSymbolAddress(&pAlo, g_Alo);
    cudaGetSymbolAddress(&pWhi, g_Whi);
    cudaGetSymbolAddress(&pWlo, g_Wlo);
    float* xg = (float*)pxg;
    float* hout = (float*)phout;
    __nv_bfloat16* Ahi = (__nv_bfloat16*)pAhi;
    __nv_bfloat16* Alo = (__nv_bfloat16*)pAlo;
    __nv_bfloat16* Whi = (__nv_bfloat16*)pWhi;
    __nv_bfloat16* Wlo = (__nv_bfloat16*)pWlo;

    static int s_attr_done = 0;
    if (!s_attr_done) {
        cudaFuncSetAttribute(gemm_mma, cudaFuncAttributeMaxDynamicSharedMemorySize, GM_SMEM);
        s_attr_done = 1;
    }

    // ---- Layer 0 ----
    split_bf16<<<4096, 256>>>(x, Ahi, Alo, (size_t)MROWS * IDIM / 2);
    split_bf16<<<2048, 256>>>(Wih0, Whi, Wlo, (size_t)G4 * IDIM / 2);
    gemm_mma<<<dim3(G4 / 128, MROWS / 128), 256, GM_SMEM>>>(
        Ahi, Alo, Whi, Wlo, bih0, bhh0, xg, IDIM, G4, 1);
    lstm_scan<<<128, 256>>>(Whh0);

    // ---- Layer 1 ----
    split_bf16<<<4096, 256>>>(hout, Ahi, Alo, (size_t)MROWS * HDIM / 2);
    split_bf16<<<2048, 256>>>(Wih1, Whi, Wlo, (size_t)G4 * HDIM / 2);
    gemm_mma<<<dim3(G4 / 128, MROWS / 128), 256, GM_SMEM>>>(
        Ahi, Alo, Whi, Wlo, bih1, bhh1, xg, HDIM, G4, 1);
    lstm_scan<<<128, 256>>>(Whh1);

    // ---- Output linear ----
    split_bf16<<<4096, 256>>>(hout, Ahi, Alo, (size_t)MROWS * HDIM / 2);
    split_bf16<<<1024, 256>>>(Wlin, Whi, Wlo, (size_t)ODIM * HDIM / 2);
    gemm_mma<<<dim3(ODIM / 128, MROWS / 128), 256, GM_SMEM>>>(
        Ahi, Alo, Whi, Wlo, blin, nullptr, out, HDIM, ODIM, 0);
}

// round 15
// speedup vs baseline: 1.2880x; 1.2880x over previous
#include <cuda_runtime.h>
#include <cuda_bf16.h>
#include <math.h>
#include <stdint.h>

// Problem dims (fixed)
#define BDIM 128
#define TDIM 512
#define IDIM 512
#define HDIM 1024
#define G4   4096
#define ODIM 512
#define MROWS (BDIM * TDIM)  // 65536

typedef unsigned long long ull;

// Packed dual-fp32 FMA (B300 FFMA2) — exact fp32, 2x throughput, only via PTX.
__device__ __forceinline__ void ffma2(ull& d, ull a, ull b) {
    asm("fma.rn.f32x2 %0, %1, %2, %0;" : "+l"(d) : "l"(a), "l"(b));
}
__device__ __forceinline__ float lo32(ull u) { return __uint_as_float((unsigned)u); }
__device__ __forceinline__ float hi32(ull u) { return __uint_as_float((unsigned)(u >> 32)); }

// ---------------- Scratch (static device allocations; no cudaMalloc) ----------
__device__ float g_xg[(size_t)TDIM * BDIM * G4];     // [T,B,4H] 1 GiB
__device__ float g_hout[(size_t)BDIM * TDIM * HDIM]; // [B,T,H] 256 MiB
__device__ float g_hA[BDIM * HDIM];                  // recurrent h double buffer
__device__ float g_hB[BDIM * HDIM];
// bf16 split-precision operands for tensor-core GEMMs
__device__ __nv_bfloat16 g_Ahi[(size_t)MROWS * HDIM];  // 128 MiB
__device__ __nv_bfloat16 g_Alo[(size_t)MROWS * HDIM];  // 128 MiB
__device__ __nv_bfloat16 g_Whi[(size_t)G4 * HDIM];     // 8 MiB
__device__ __nv_bfloat16 g_Wlo[(size_t)G4 * HDIM];     // 8 MiB

// ---------------- Split grid barrier (arrive / wait) -----------------------
__device__ unsigned g_cnt = 0;
__device__ volatile unsigned g_gen = 0;

__device__ __forceinline__ void gb_arrive(unsigned nb) {
    __threadfence();
    __syncthreads();
    if (threadIdx.x == 0) {
        unsigned old = atomicAdd(&g_cnt, 1u);
        if (old == nb - 1u) {
            g_cnt = 0;
            __threadfence();
            g_gen = g_gen + 1u;
        }
    }
}
__device__ __forceinline__ void gb_wait(unsigned target) {
    if (threadIdx.x == 0) {
        while ((int)(g_gen - target) < 0) { }
    }
    __syncthreads();
}

__device__ __forceinline__ float sigmoidf_(float x) {
    return 1.0f / (1.0f + __expf(-x));
}

// ===================== baseline-PTX tensor-core helpers ====================
__device__ __forceinline__ uint32_t smem_u32(const void* p) {
    uint32_t a;
    asm("{ .reg .u64 t; cvta.to.shared.u64 t, %1; cvt.u32.u64 %0, t; }" : "=r"(a) : "l"(p));
    return a;
}
#define SWZ(o) ((o) ^ ((((unsigned)(o)) >> 3) & 0x70u))

__device__ __forceinline__ void ldsm_x4(uint32_t r[4], uint32_t addr) {
    asm volatile("ldmatrix.sync.aligned.m8n8.x4.shared.b16 {%0,%1,%2,%3}, [%4];"
                 : "=r"(r[0]), "=r"(r[1]), "=r"(r[2]), "=r"(r[3]) : "r"(addr));
}
__device__ __forceinline__ void mma_bf16(float c[4], const uint32_t a[4], const uint32_t b[2]) {
    asm volatile(
        "mma.sync.aligned.m16n8k16.row.col.f32.bf16.bf16.f32 "
        "{%0,%1,%2,%3}, {%4,%5,%6,%7}, {%8,%9}, {%0,%1,%2,%3};"
        : "+f"(c[0]), "+f"(c[1]), "+f"(c[2]), "+f"(c[3])
        : "r"(a[0]), "r"(a[1]), "r"(a[2]), "r"(a[3]), "r"(b[0]), "r"(b[1]));
}
__device__ __forceinline__ void cp16(uint32_t saddr, const void* g) {
    asm volatile("cp.async.cg.shared.global [%0], [%1], 16;" :: "r"(saddr), "l"(g));
}
#define CP_COMMIT() asm volatile("cp.async.commit_group;" ::: "memory")
#define CP_WAIT(n)  asm volatile("cp.async.wait_group %0;" :: "n"(n) : "memory")

// ---------------- bf16 split kernel ----------------------------------------
__global__ void split_bf16(const float* __restrict__ in,
                           __nv_bfloat16* __restrict__ hi,
                           __nv_bfloat16* __restrict__ lo, size_t n2) {
    size_t i = (size_t)blockIdx.x * blockDim.x + threadIdx.x;
    size_t stride = (size_t)gridDim.x * blockDim.x;
    const float2* in2 = (const float2*)in;
    __nv_bfloat162* h2 = (__nv_bfloat162*)hi;
    __nv_bfloat162* l2 = (__nv_bfloat162*)lo;
    for (; i < n2; i += stride) {
        float2 v = in2[i];
        __nv_bfloat16 hx = __float2bfloat16_rn(v.x);
        __nv_bfloat16 hy = __float2bfloat16_rn(v.y);
        float lx = v.x - __bfloat162float(hx);
        float ly = v.y - __bfloat162float(hy);
        __nv_bfloat162 hh; hh.x = hx; hh.y = hy;
        __nv_bfloat162 ll; ll.x = __float2bfloat16_rn(lx); ll.y = __float2bfloat16_rn(ly);
        h2[i] = hh;
        l2[i] = ll;
    }
}

// ---------------- HMMA split-precision GEMM (unchanged from R10) -----------
#define GM_TILE_B   16384                 // 128 rows x 128 bytes
#define GM_STAGE_B  (4 * GM_TILE_B)       // 64 KiB
#define GM_SMEM     (1024 + 2 * GM_STAGE_B)

__global__ __launch_bounds__(256, 1) void gemm_mma(
    const __nv_bfloat16* __restrict__ Ahi, const __nv_bfloat16* __restrict__ Alo,
    const __nv_bfloat16* __restrict__ Bhi, const __nv_bfloat16* __restrict__ Blo,
    const float* __restrict__ b1, const float* __restrict__ b2,
    float* __restrict__ C, int K, int N, int swap)
{
    extern __shared__ char dsm[];
    const int tid = threadIdx.x;
    const int lane = tid & 31;
    const int warp = tid >> 5;
    const int m0 = blockIdx.y << 7;
    const int n0 = blockIdx.x << 7;
    const int wm = (warp >> 1) << 5;   // 0,32,64,96
    const int wn = (warp & 1) << 6;    // 0,64

    uint32_t sb = (smem_u32(dsm) + 1023u) & ~1023u;

    const int lrow = tid & 127;
    const int lcp  = (tid >> 7) << 2;  // chunk base 0 or 4 (x16B)

    auto load_tile = [&](uint32_t sdst, const __nv_bfloat16* gsrc, int row0, int kc) {
        const __nv_bfloat16* g = gsrc + (size_t)(row0 + lrow) * K + kc * 64 + lcp * 8;
        uint32_t ob = (uint32_t)lrow * 128u + (uint32_t)lcp * 16u;
#pragma unroll
        for (int j = 0; j < 4; j++)
            cp16(sdst + SWZ(ob + j * 16u), g + j * 8);
    };
    auto load_stage = [&](uint32_t stage, int kc) {
        uint32_t base = sb + stage * GM_STAGE_B;
        load_tile(base,                Ahi, m0, kc);
        load_tile(base + GM_TILE_B,    Alo, m0, kc);
        load_tile(base + 2 * GM_TILE_B, Bhi, n0, kc);
        load_tile(base + 3 * GM_TILE_B, Blo, n0, kc);
        CP_COMMIT();
    };

    float acc[2][8][4];
#pragma unroll
    for (int mf = 0; mf < 2; mf++)
#pragma unroll
        for (int f = 0; f < 8; f++)
#pragma unroll
            for (int e = 0; e < 4; e++) acc[mf][f][e] = 0.0f;

    const uint32_t a_off = (uint32_t)(wm + (lane & 15)) * 128u + (uint32_t)(lane >> 4) * 16u;
    const uint32_t b_row = (uint32_t)(wn + ((lane >> 4) << 3) + (lane & 7));
    const uint32_t b_off = b_row * 128u + (uint32_t)((lane >> 3) & 1) * 16u;

    const int nc = K >> 6;
    load_stage(0, 0);

#pragma unroll 1
    for (int c = 0; c < nc; ++c) {
        if (c + 1 < nc) load_stage((c + 1) & 1, c + 1);
        if (c + 1 < nc) { CP_WAIT(1); } else { CP_WAIT(0); }
        __syncthreads();

        uint32_t base = sb + (uint32_t)(c & 1) * GM_STAGE_B;
        uint32_t pAh = base;
        uint32_t pAl = base + GM_TILE_B;
        uint32_t pBh = base + 2 * GM_TILE_B;
        uint32_t pBl = base + 3 * GM_TILE_B;

#pragma unroll
        for (int ks = 0; ks < 4; ks++) {
            uint32_t ko = (uint32_t)ks * 32u;
            uint32_t ahi[2][4], alo[2][4];
#pragma unroll
            for (int mf = 0; mf < 2; mf++) {
                uint32_t off = a_off + (uint32_t)(mf << 11) + ko;
                ldsm_x4(ahi[mf], pAh + SWZ(off));
                ldsm_x4(alo[mf], pAl + SWZ(off));
            }
            uint32_t bhi[8][2], blo[8][2];
#pragma unroll
            for (int nq = 0; nq < 4; nq++) {
                uint32_t off = b_off + (uint32_t)(nq << 11) + ko;
                uint32_t r[4];
                ldsm_x4(r, pBh + SWZ(off));
                bhi[2 * nq][0] = r[0]; bhi[2 * nq][1] = r[1];
                bhi[2 * nq + 1][0] = r[2]; bhi[2 * nq + 1][1] = r[3];
                ldsm_x4(r, pBl + SWZ(off));
                blo[2 * nq][0] = r[0]; blo[2 * nq][1] = r[1];
                blo[2 * nq + 1][0] = r[2]; blo[2 * nq + 1][1] = r[3];
            }
#pragma unroll
            for (int mf = 0; mf < 2; mf++)
#pragma unroll
                for (int f = 0; f < 8; f++) {
                    mma_bf16(acc[mf][f], ahi[mf], bhi[f]);
                    mma_bf16(acc[mf][f], ahi[mf], blo[f]);
                    mma_bf16(acc[mf][f], alo[mf], bhi[f]);
                }
        }
        __syncthreads();
    }

#pragma unroll
    for (int mf = 0; mf < 2; mf++) {
        int mA = m0 + wm + mf * 16 + (lane >> 2);
        int mB = mA + 8;
        int rA = swap ? ((mA & (TDIM - 1)) * BDIM + (mA >> 9)) : mA;
        int rB = swap ? ((mB & (TDIM - 1)) * BDIM + (mB >> 9)) : mB;
        float* CA = C + (size_t)rA * N;
        float* CB = C + (size_t)rB * N;
#pragma unroll
        for (int f = 0; f < 8; f++) {
            int n = n0 + wn + f * 8 + ((lane & 3) << 1);
            float bb0 = b1[n] + (b2 ? b2[n] : 0.0f);
            float bb1 = b1[n + 1] + (b2 ? b2[n + 1] : 0.0f);
            float2 v0 = make_float2(acc[mf][f][0] + bb0, acc[mf][f][1] + bb1);
            float2 v1 = make_float2(acc[mf][f][2] + bb0, acc[mf][f][3] + bb1);
            *(float2*)(CA + n) = v0;
            *(float2*)(CB + n) = v1;
        }
    }
}

// ---------------- Persistent LSTM scan (FFMA2, pipelined fragments) --------
// 128 CTAs (4 b-tiles x 32 h-tiles) x 128 threads. Warp -> 8 b-rows,
// lane -> 4 cols. Inner loop: rolling register double-buffer of smem
// fragments (load k+1 before FMAs of k) to hide the 29-cyc LDS latency
// at 1 warp/SMSP. Barrier split: arrive after h-stores, wait after issuing
// the h-independent W/xg loads of the next step.
__global__ __launch_bounds__(128, 1) void lstm_scan(const float* __restrict__ Whh)
{
    __shared__ alignas(16) float AsD[2][16][68];   // dup A: [k][2*row(+0/1)], pad
    __shared__ alignas(16) float Bs[2][16][132];   // [k][col], pad (16B rows)
    __shared__ alignas(16) float gsm[32][128];     // gates staging
    __shared__ float csm[32][32];                  // cell state (persistent)

    const int tid = threadIdx.x;
    const int b0 = (blockIdx.x >> 5) << 5;
    const int h0 = (blockIdx.x & 31) << 5;
    const unsigned nb = gridDim.x;

    const unsigned gbase = g_gen;   // consistent: read before any arrive

    // zero c and the initial h buffer (this CTA's (b,h) block)
    for (int q = tid; q < 1024; q += 128) {
        csm[q >> 5][q & 31] = 0.0f;
        g_hA[(b0 + (q >> 5)) * HDIM + h0 + (q & 31)] = 0.0f;
    }
    gb_arrive(nb);

    const int w = tid >> 5;
    const int l = tid & 31;
    const int ab = tid >> 2;
    const int ak = (tid & 3) << 2;
    const int colq = ab;
    const int kb = ak;
    const float* Wp0 = Whh + ((size_t)(0 * HDIM + h0 + colq)) * HDIM + kb;
    const float* Wp1 = Whh + ((size_t)(1 * HDIM + h0 + colq)) * HDIM + kb;
    const float* Wp2 = Whh + ((size_t)(2 * HDIM + h0 + colq)) * HDIM + kb;
    const float* Wp3 = Whh + ((size_t)(3 * HDIM + h0 + colq)) * HDIM + kb;
    const int eb = tid >> 2;
    const int eh = (tid & 3) << 3;

#pragma unroll 1
    for (int t = 0; t < TDIM; ++t) {
        const float* hp = (t & 1) ? g_hB : g_hA;
        float* hn = (t & 1) ? g_hA : g_hB;
        const float* Ap = hp + (b0 + ab) * HDIM + ak;

        // ---- h-independent work BEFORE the barrier wait ----
        // xg prefetch (DRAM latency overlaps barrier + k-loop)
        const size_t xb = ((size_t)t * BDIM + b0 + eb) * G4 + h0 + eh;
        float4 xi0 = __ldcs((const float4*)&g_xg[xb]);
        float4 xi1 = __ldcs((const float4*)&g_xg[xb + 4]);
        float4 xf0 = __ldcs((const float4*)&g_xg[xb + 1024]);
        float4 xf1 = __ldcs((const float4*)&g_xg[xb + 1028]);
        float4 xg0 = __ldcs((const float4*)&g_xg[xb + 2048]);
        float4 xg1 = __ldcs((const float4*)&g_xg[xb + 2052]);
        float4 xo0 = __ldcs((const float4*)&g_xg[xb + 3072]);
        float4 xo1 = __ldcs((const float4*)&g_xg[xb + 3076]);

        // W tile-0 load + store to smem (W is step-invariant; buffer is free:
        // all threads passed the previous arrive's __syncthreads)
        {
            float4 rb0 = *(const float4*)Wp0;
            float4 rb1 = *(const float4*)Wp1;
            float4 rb2 = *(const float4*)Wp2;
            float4 rb3 = *(const float4*)Wp3;
            Bs[0][kb + 0][colq]      = rb0.x; Bs[0][kb + 1][colq]      = rb0.y;
            Bs[0][kb + 2][colq]      = rb0.z; Bs[0][kb + 3][colq]      = rb0.w;
            Bs[0][kb + 0][colq + 32] = rb1.x; Bs[0][kb + 1][colq + 32] = rb1.y;
            Bs[0][kb + 2][colq + 32] = rb1.z; Bs[0][kb + 3][colq + 32] = rb1.w;
            Bs[0][kb + 0][colq + 64] = rb2.x; Bs[0][kb + 1][colq + 64] = rb2.y;
            Bs[0][kb + 2][colq + 64] = rb2.z; Bs[0][kb + 3][colq + 64] = rb2.w;
            Bs[0][kb + 0][colq + 96] = rb3.x; Bs[0][kb + 1][colq + 96] = rb3.y;
            Bs[0][kb + 2][colq + 96] = rb3.z; Bs[0][kb + 3][colq + 96] = rb3.w;
        }

        // ---- wait for h(t-1) from all CTAs ----
        gb_wait(gbase + t + 1);

        // A tile-0 load + dup store
        {
            float4 ra = __ldcg((const float4*)Ap);
            AsD[0][ak + 0][2 * ab] = ra.x; AsD[0][ak + 0][2 * ab + 1] = ra.x;
            AsD[0][ak + 1][2 * ab] = ra.y; AsD[0][ak + 1][2 * ab + 1] = ra.y;
            AsD[0][ak + 2][2 * ab] = ra.z; AsD[0][ak + 2][2 * ab + 1] = ra.z;
            AsD[0][ak + 3][2 * ab] = ra.w; AsD[0][ak + 3][2 * ab + 1] = ra.w;
        }
        __syncthreads();

        ull acc[8][2];
#pragma unroll
        for (int i = 0; i < 8; i++) { acc[i][0] = 0ULL; acc[i][1] = 0ULL; }

        // initial fragments (k = 0 of tile 0)
        ulonglong2 fq0 = *(const ulonglong2*)&AsD[0][0][16 * w];
        ulonglong2 fq1 = *(const ulonglong2*)&AsD[0][0][16 * w + 4];
        ulonglong2 fq2 = *(const ulonglong2*)&AsD[0][0][16 * w + 8];
        ulonglong2 fq3 = *(const ulonglong2*)&AsD[0][0][16 * w + 12];
        ulonglong2 fbb = *(const ulonglong2*)&Bs[0][0][4 * l];

        float4 ra2, rc0, rc1, rc2, rc3;
        int cur = 0;
#pragma unroll 1
        for (int kt = 0; kt < 64; ++kt) {
            if (kt < 63) {
                int ko = (kt + 1) << 4;
                ra2 = __ldcg((const float4*)(Ap + ko));
                rc0 = *(const float4*)(Wp0 + ko);
                rc1 = *(const float4*)(Wp1 + ko);
                rc2 = *(const float4*)(Wp2 + ko);
                rc3 = *(const float4*)(Wp3 + ko);
            }
#pragma unroll
            for (int k = 0; k < 16; ++k) {
                ulonglong2 nq0, nq1, nq2, nq3, nbb;
                if (k < 15) {
                    nq0 = *(const ulonglong2*)&AsD[cur][k + 1][16 * w];
                    nq1 = *(const ulonglong2*)&AsD[cur][k + 1][16 * w + 4];
                    nq2 = *(const ulonglong2*)&AsD[cur][k + 1][16 * w + 8];
                    nq3 = *(const ulonglong2*)&AsD[cur][k + 1][16 * w + 12];
                    nbb = *(const ulonglong2*)&Bs[cur][k + 1][4 * l];
                }
                ffma2(acc[0][0], fq0.x, fbb.x); ffma2(acc[0][1], fq0.x, fbb.y);
                ffma2(acc[1][0], fq0.y, fbb.x); ffma2(acc[1][1], fq0.y, fbb.y);
                ffma2(acc[2][0], fq1.x, fbb.x); ffma2(acc[2][1], fq1.x, fbb.y);
                ffma2(acc[3][0], fq1.y, fbb.x); ffma2(acc[3][1], fq1.y, fbb.y);
                ffma2(acc[4][0], fq2.x, fbb.x); ffma2(acc[4][1], fq2.x, fbb.y);
                ffma2(acc[5][0], fq2.y, fbb.x); ffma2(acc[5][1], fq2.y, fbb.y);
                ffma2(acc[6][0], fq3.x, fbb.x); ffma2(acc[6][1], fq3.x, fbb.y);
                ffma2(acc[7][0], fq3.y, fbb.x); ffma2(acc[7][1], fq3.y, fbb.y);
                if (k < 15) { fq0 = nq0; fq1 = nq1; fq2 = nq2; fq3 = nq3; fbb = nbb; }
            }
            if (kt < 63) {
                cur ^= 1;
                AsD[cur][ak + 0][2 * ab] = ra2.x; AsD[cur][ak + 0][2 * ab + 1] = ra2.x;
                AsD[cur][ak + 1][2 * ab] = ra2.y; AsD[cur][ak + 1][2 * ab + 1] = ra2.y;
                AsD[cur][ak + 2][2 * ab] = ra2.z; AsD[cur][ak + 2][2 * ab + 1] = ra2.z;
                AsD[cur][ak + 3][2 * ab] = ra2.w; AsD[cur][ak + 3][2 * ab + 1] = ra2.w;
                Bs[cur][kb + 0][colq]      = rc0.x; Bs[cur][kb + 1][colq]      = rc0.y;
                Bs[cur][kb + 2][colq]      = rc0.z; Bs[cur][kb + 3][colq]      = rc0.w;
                Bs[cur][kb + 0][colq + 32] = rc1.x; Bs[cur][kb + 1][colq + 32] = rc1.y;
                Bs[cur][kb + 2][colq + 32] = rc1.z; Bs[cur][kb + 3][colq + 32] = rc1.w;
                Bs[cur][kb + 0][colq + 64] = rc2.x; Bs[cur][kb + 1][colq + 64] = rc2.y;
                Bs[cur][kb + 2][colq + 64] = rc2.z; Bs[cur][kb + 3][colq + 64] = rc2.w;
                Bs[cur][kb + 0][colq + 96] = rc3.x; Bs[cur][kb + 1][colq + 96] = rc3.y;
                Bs[cur][kb + 2][colq + 96] = rc3.z; Bs[cur][kb + 3][colq + 96] = rc3.w;
                __syncthreads();
                fq0 = *(const ulonglong2*)&AsD[cur][0][16 * w];
                fq1 = *(const ulonglong2*)&AsD[cur][0][16 * w + 4];
                fq2 = *(const ulonglong2*)&AsD[cur][0][16 * w + 8];
                fq3 = *(const ulonglong2*)&AsD[cur][0][16 * w + 12];
                fbb = *(const ulonglong2*)&Bs[cur][0][4 * l];
            }
        }

        // stage gates to smem for the gate-regrouped elementwise
#pragma unroll
        for (int i = 0; i < 8; i++) {
            *(float4*)&gsm[8 * w + i][4 * l] =
                make_float4(lo32(acc[i][0]), hi32(acc[i][0]),
                            lo32(acc[i][1]), hi32(acc[i][1]));
        }
        __syncthreads();

        {
            const float* pxi0 = (const float*)&xi0; const float* pxi1 = (const float*)&xi1;
            const float* pxf0 = (const float*)&xf0; const float* pxf1 = (const float*)&xf1;
            const float* pxg0 = (const float*)&xg0; const float* pxg1 = (const float*)&xg1;
            const float* pxo0 = (const float*)&xo0; const float* pxo1 = (const float*)&xo1;

            float h8[8];
#pragma unroll
            for (int q = 0; q < 8; q++) {
                int hh = eh + q;
                float vxi = (q < 4) ? pxi0[q] : pxi1[q - 4];
                float vxf = (q < 4) ? pxf0[q] : pxf1[q - 4];
                float vxg = (q < 4) ? pxg0[q] : pxg1[q - 4];
                float vxo = (q < 4) ? pxo0[q] : pxo1[q - 4];
                float gi = gsm[eb][hh]      + vxi;
                float gf = gsm[eb][32 + hh] + vxf;
                float gg = gsm[eb][64 + hh] + vxg;
                float go = gsm[eb][96 + hh] + vxo;
                gi = sigmoidf_(gi);
                gf = sigmoidf_(gf);
                gg = tanhf(gg);
                go = sigmoidf_(go);
                float c = fmaf(gf, csm[eb][hh], gi * gg);
                csm[eb][hh] = c;
                h8[q] = go * tanhf(c);
            }
            float4 hv0 = make_float4(h8[0], h8[1], h8[2], h8[3]);
            float4 hv1 = make_float4(h8[4], h8[5], h8[6], h8[7]);
            float* hnp = hn + (b0 + eb) * HDIM + h0 + eh;
            *(float4*)hnp = hv0;
            *(float4*)(hnp + 4) = hv1;
            float* hop = g_hout + ((size_t)(b0 + eb) * TDIM + t) * HDIM + h0 + eh;
            *(float4*)hop = hv0;
            *(float4*)(hop + 4) = hv1;
        }

        if (t < TDIM - 1) gb_arrive(nb);
    }
}

// ---------------- Launch orchestration -------------------------------------
extern "C" void kernel_launch(void* const* d_in, const int* in_sizes, int n_in,
                              void* d_out, int out_size)
{
    (void)in_sizes; (void)n_in; (void)out_size;
    const float* x    = (const float*)d_in[0];
    const float* Wih0 = (const float*)d_in[1];
    const float* Whh0 = (const float*)d_in[2];
    const float* bih0 = (const float*)d_in[3];
    const float* bhh0 = (const float*)d_in[4];
    const float* Wih1 = (const float*)d_in[5];
    const float* Whh1 = (const float*)d_in[6];
    const float* bih1 = (const float*)d_in[7];
    const float* bhh1 = (const float*)d_in[8];
    const float* Wlin = (const float*)d_in[9];
    const float* blin = (const float*)d_in[10];
    float* out = (float*)d_out;

    void *pxg = nullptr, *phout = nullptr;
    void *pAhi = nullptr, *pAlo = nullptr, *pWhi = nullptr, *pWlo = nullptr;
    cudaGetSymbolAddress(&pxg, g_xg);
    cudaGetSymbolAddress(&phout, g_hout);
    cudaGetSymbolAddress(&pAhi, g_Ahi);
    cudaGetSymbolAddress(&pAlo, g_Alo);
    cudaGetSymbolAddress(&pWhi, g_Whi);
    cudaGetSymbolAddress(&pWlo, g_Wlo);
    float* xg = (float*)pxg;
    float* hout = (float*)phout;
    __nv_bfloat16* Ahi = (__nv_bfloat16*)pAhi;
    __nv_bfloat16* Alo = (__nv_bfloat16*)pAlo;
    __nv_bfloat16* Whi = (__nv_bfloat16*)pWhi;
    __nv_bfloat16* Wlo = (__nv_bfloat16*)pWlo;

    static int s_attr_done = 0;
    if (!s_attr_done) {
        cudaFuncSetAttribute(gemm_mma, cudaFuncAttributeMaxDynamicSharedMemorySize, GM_SMEM);
        s_attr_done = 1;
    }

    // ---- Layer 0 ----
    split_bf16<<<4096, 256>>>(x, Ahi, Alo, (size_t)MROWS * IDIM / 2);
    split_bf16<<<2048, 256>>>(Wih0, Whi, Wlo, (size_t)G4 * IDIM / 2);
    gemm_mma<<<dim3(G4 / 128, MROWS / 128), 256, GM_SMEM>>>(
        Ahi, Alo, Whi, Wlo, bih0, bhh0, xg, IDIM, G4, 1);
    lstm_scan<<<128, 128>>>(Whh0);

    // ---- Layer 1 ----
    split_bf16<<<4096, 256>>>(hout, Ahi, Alo, (size_t)MROWS * HDIM / 2);
    split_bf16<<<2048, 256>>>(Wih1, Whi, Wlo, (size_t)G4 * HDIM / 2);
    gemm_mma<<<dim3(G4 / 128, MROWS / 128), 256, GM_SMEM>>>(
        Ahi, Alo, Whi, Wlo, bih1, bhh1, xg, HDIM, G4, 1);
    lstm_scan<<<128, 128>>>(Whh1);

    // ---- Output linear ----
    split_bf16<<<4096, 256>>>(hout, Ahi, Alo, (size_t)MROWS * HDIM / 2);
    split_bf16<<<1024, 256>>>(Wlin, Whi, Wlo, (size_t)ODIM * HDIM / 2);
    gemm_mma<<<dim3(ODIM / 128, MROWS / 128), 256, GM_SMEM>>>(
        Ahi, Alo, Whi, Wlo, blin, nullptr, out, HDIM, ODIM, 0);
}